// round 7
// baseline (speedup 1.0000x reference)
#include <cuda_runtime.h>
#include <cuda_fp16.h>
#include <mma.h>
#include <math.h>

using namespace nvcuda;

#define N_NODES 50000
#define E_EDGES 800000
#define DIM 128
#define NHEAD 8
#define HDIM 16
#define LN_EPS 1e-5f
#define FULLMASK 0xFFFFFFFFu
#define NB_PER_G ((N_NODES + 255) / 256)   // 196 blocks of 256 nodes per graph

// Scratch (static __device__ arrays: allocation-free per harness rules)
__device__ __half2 d_xh[N_NODES * 64];   // fp16 gather input
__device__ float  d_agg[N_NODES * DIM];  // edge-aggregated features (fp32)
__device__ int    d_deg[4 * N_NODES];    // [src1 | dst1 | src2 | dst2] degrees
__device__ float  d_norm[4 * N_NODES];   // rsqrt norms, same layout
__device__ int    d_off[2 * N_NODES];    // CSR row offsets [dst1 | dst2]
__device__ int    d_cur[2 * N_NODES];    // scatter cursors
__device__ int    d_csr[2 * E_EDGES];    // CSR column (source-node) ids [g1 | g2]
__device__ int    d_bsum[2 * NB_PER_G];  // per-block dst-degree sums
__device__ __half d_wh[2 * DIM * DIM];   // fp16 W1 | W2

// ---------------------------------------------------------------------------
__global__ void zero_deg_kernel() {
    int i = blockIdx.x * blockDim.x + threadIdx.x;
    if (i < 4 * N_NODES) d_deg[i] = 0;
}

__global__ void degrees_kernel(const int* __restrict__ s1, const int* __restrict__ t1,
                               const int* __restrict__ s2, const int* __restrict__ t2) {
    int i = blockIdx.x * blockDim.x + threadIdx.x;
    if (i >= E_EDGES) return;
    atomicAdd(&d_deg[0 * N_NODES + s1[i]], 1);
    atomicAdd(&d_deg[1 * N_NODES + t1[i]], 1);
    atomicAdd(&d_deg[2 * N_NODES + s2[i]], 1);
    atomicAdd(&d_deg[3 * N_NODES + t2[i]], 1);
}

// ---------------------------------------------------------------------------
// Fused: norms for all 4 segments + per-block dst-degree sums (segments 1,3).
// ---------------------------------------------------------------------------
__global__ void __launch_bounds__(256) norm_bsum_kernel() {
    int seg = blockIdx.x / NB_PER_G;          // 0:src1 1:dst1 2:src2 3:dst2
    int b   = blockIdx.x % NB_PER_G;
    int n   = b * 256 + threadIdx.x;
    int d = 0;
    if (n < N_NODES) {
        d = d_deg[seg * N_NODES + n];
        d_norm[seg * N_NODES + n] = (d > 0) ? rsqrtf((float)d) : 0.f;
    }
    if (seg == 1 || seg == 3) {
        int v = d;
#pragma unroll
        for (int o = 16; o > 0; o >>= 1) v += __shfl_down_sync(FULLMASK, v, o);
        __shared__ int ws[8];
        if ((threadIdx.x & 31) == 0) ws[threadIdx.x >> 5] = v;
        __syncthreads();
        if (threadIdx.x < 8) {
            int s = ws[threadIdx.x];
#pragma unroll
            for (int o = 4; o > 0; o >>= 1) s += __shfl_down_sync(0xFFu, s, o);
            if (threadIdx.x == 0) d_bsum[(seg >> 1) * NB_PER_G + b] = s;
        }
    }
}

// ---------------------------------------------------------------------------
// Offsets: inline prefix over d_bsum + block-local exclusive scan.
// ---------------------------------------------------------------------------
__global__ void __launch_bounds__(256) offsets_kernel() {
    __shared__ int ws[8];
    __shared__ int sbase;
    int g = blockIdx.x / NB_PER_G;
    int b = blockIdx.x % NB_PER_G;
    int degoff = (g == 0 ? 1 : 3) * N_NODES;
    int t = threadIdx.x;
    int lane = t & 31, w = t >> 5;

    {
        int v = (t < b) ? d_bsum[g * NB_PER_G + t] : 0;
#pragma unroll
        for (int o = 16; o > 0; o >>= 1) v += __shfl_down_sync(FULLMASK, v, o);
        if (lane == 0) ws[w] = v;
        __syncthreads();
        if (t < 8) {
            int s = ws[t];
#pragma unroll
            for (int o = 4; o > 0; o >>= 1) s += __shfl_down_sync(0xFFu, s, o);
            if (t == 0) sbase = s;
        }
        __syncthreads();
    }
    int blockbase = sbase;
    __syncthreads();

    int n = b * 256 + t;
    int v = (n < N_NODES) ? d_deg[degoff + n] : 0;
    int x = v;
#pragma unroll
    for (int o = 1; o < 32; o <<= 1) {
        int y = __shfl_up_sync(FULLMASK, x, o);
        if (lane >= o) x += y;
    }
    if (lane == 31) ws[w] = x;
    __syncthreads();
    if (t < 8) {
        int s = ws[t];
#pragma unroll
        for (int o = 1; o < 8; o <<= 1) {
            int y = __shfl_up_sync(0xFFu, s, o);
            if (t >= o) s += y;
        }
        ws[t] = s;
    }
    __syncthreads();
    int base = blockbase + ((w > 0) ? ws[w - 1] : 0);
    if (n < N_NODES) {
        int off = base + x - v;   // exclusive
        d_off[g * N_NODES + n] = off;
        d_cur[g * N_NODES + n] = off;
    }
}

// ---------------------------------------------------------------------------
// Fused scatter + feature convert + weight convert.
// Blocks [0, SCAT): CSR scatter (one edge per thread).
// Blocks [SCAT, +CONV): feat*norm_src1 -> fp16 d_xh.
// Blocks [SCAT+CONV, +WCONV): W1|W2 fp32 -> fp16 d_wh.
// ---------------------------------------------------------------------------
#define SCAT_BLOCKS ((2 * E_EDGES) / 256)        // 6250
#define CONV_BLOCKS ((N_NODES * 32 + 255) / 256) // 6250
#define WCONV_BLOCKS ((2 * DIM * DIM / 4) / 256) // 32
__global__ void scatter_convert_kernel(const int* __restrict__ s1, const int* __restrict__ t1,
                                       const int* __restrict__ s2, const int* __restrict__ t2,
                                       const float* __restrict__ feat,
                                       const float* __restrict__ W1,
                                       const float* __restrict__ W2) {
    int bid = blockIdx.x;
    if (bid < SCAT_BLOCKS) {
        int i = bid * 256 + threadIdx.x;
        if (i < E_EDGES) {
            int p = atomicAdd(&d_cur[0 * N_NODES + t1[i]], 1);
            d_csr[p] = s1[i];
        } else {
            int e = i - E_EDGES;
            int p = atomicAdd(&d_cur[1 * N_NODES + t2[e]], 1);
            d_csr[E_EDGES + p] = s2[e];
        }
    } else if (bid < SCAT_BLOCKS + CONV_BLOCKS) {
        int i = (bid - SCAT_BLOCKS) * 256 + threadIdx.x;
        if (i >= N_NODES * 32) return;
        int n = i >> 5, c4 = i & 31;
        float nm = d_norm[n];                       // src1 norms at offset 0
        float4 v = ((const float4*)feat)[i];
        __half2 h0 = __floats2half2_rn(v.x * nm, v.y * nm);
        __half2 h1 = __floats2half2_rn(v.z * nm, v.w * nm);
        uint2 st;
        st.x = *(unsigned int*)&h0;
        st.y = *(unsigned int*)&h1;
        *(uint2*)(d_xh + n * 64 + c4 * 2) = st;
    } else {
        int i = (bid - SCAT_BLOCKS - CONV_BLOCKS) * 256 + threadIdx.x;  // float4 idx
        const float* W = (i < 4096) ? W1 : W2;
        int li = (i < 4096) ? i : i - 4096;
        float4 v = ((const float4*)W)[li];
        __half2 h0 = __floats2half2_rn(v.x, v.y);
        __half2 h1 = __floats2half2_rn(v.z, v.w);
        uint2 st;
        st.x = *(unsigned int*)&h0;
        st.y = *(unsigned int*)&h1;
        *(uint2*)(d_wh + i * 4) = st;
    }
}

// ---------------------------------------------------------------------------
// Half-warp-per-node CSR gather: 16 lanes own a 256B fp16 row (16B/lane via
// uint4). 4 sources in flight per node => 8 outstanding loads per warp.
// fp32 accumulation.
// ---------------------------------------------------------------------------
__device__ __forceinline__ void acc_half16(float4& a0, float4& a1, uint4 r) {
    __half2 h0 = *(__half2*)&r.x;
    __half2 h1 = *(__half2*)&r.y;
    __half2 h2 = *(__half2*)&r.z;
    __half2 h3 = *(__half2*)&r.w;
    float2 f0 = __half22float2(h0);
    float2 f1 = __half22float2(h1);
    float2 f2 = __half22float2(h2);
    float2 f3 = __half22float2(h3);
    a0.x += f0.x; a0.y += f0.y; a0.z += f1.x; a0.w += f1.y;
    a1.x += f2.x; a1.y += f2.y; a1.z += f3.x; a1.w += f3.y;
}

__global__ void __launch_bounds__(256) gather_kernel(int g) {
    int n = (blockIdx.x * blockDim.x + threadIdx.x) >> 4;   // half-warp per node
    if (n >= N_NODES) return;
    int lane16 = threadIdx.x & 15;
    unsigned hmask = 0xFFFFu << (threadIdx.x & 16);
    int beg = d_off[g * N_NODES + n];
    int cnt = d_deg[(g == 0 ? 1 : 3) * N_NODES + n];
    const int* csr = d_csr + g * E_EDGES;

    float4 accA0 = make_float4(0.f,0.f,0.f,0.f), accA1 = make_float4(0.f,0.f,0.f,0.f);
    float4 accB0 = make_float4(0.f,0.f,0.f,0.f), accB1 = make_float4(0.f,0.f,0.f,0.f);
    float4 accC0 = make_float4(0.f,0.f,0.f,0.f), accC1 = make_float4(0.f,0.f,0.f,0.f);
    float4 accD0 = make_float4(0.f,0.f,0.f,0.f), accD1 = make_float4(0.f,0.f,0.f,0.f);

    const __half2* base = d_xh;
    for (int j0 = 0; j0 < cnt; j0 += 16) {
        int m = min(16, cnt - j0);
        int s_l = (lane16 < m) ? csr[beg + j0 + lane16] : 0;
        int jj = 0;
        for (; jj + 3 < m; jj += 4) {
            int sA = __shfl_sync(hmask, s_l, jj,     16);
            int sB = __shfl_sync(hmask, s_l, jj + 1, 16);
            int sC = __shfl_sync(hmask, s_l, jj + 2, 16);
            int sD = __shfl_sync(hmask, s_l, jj + 3, 16);
            uint4 rA = *(const uint4*)(base + sA * 64 + lane16 * 4);
            uint4 rB = *(const uint4*)(base + sB * 64 + lane16 * 4);
            uint4 rC = *(const uint4*)(base + sC * 64 + lane16 * 4);
            uint4 rD = *(const uint4*)(base + sD * 64 + lane16 * 4);
            acc_half16(accA0, accA1, rA);
            acc_half16(accB0, accB1, rB);
            acc_half16(accC0, accC1, rC);
            acc_half16(accD0, accD1, rD);
        }
        for (; jj < m; jj++) {
            int sA = __shfl_sync(hmask, s_l, jj, 16);
            uint4 rA = *(const uint4*)(base + sA * 64 + lane16 * 4);
            acc_half16(accA0, accA1, rA);
        }
    }
    accA0.x += accB0.x + accC0.x + accD0.x;
    accA0.y += accB0.y + accC0.y + accD0.y;
    accA0.z += accB0.z + accC0.z + accD0.z;
    accA0.w += accB0.w + accC0.w + accD0.w;
    accA1.x += accB1.x + accC1.x + accD1.x;
    accA1.y += accB1.y + accC1.y + accD1.y;
    accA1.z += accB1.z + accC1.z + accD1.z;
    accA1.w += accB1.w + accC1.w + accD1.w;
    float* o = d_agg + n * DIM + lane16 * 8;
    *(float4*)o = accA0;
    *(float4*)(o + 4) = accA1;
}

// ---------------------------------------------------------------------------
// Tensor-core GEMM tile: 64 rows x 128 cols, K=128. 256 threads = 8 warps.
// W preconverted to fp16 in d_wh (w_off selects W1/W2).
// smem layout (bytes):
//   [0, 34816)       Ws_h: half[128][136]  -- later aliased by C (fp32 64x132)
//   [34816, 52224)   As_h: half[64][136]
//   [52224, 54272)   red:  float[512]
// ---------------------------------------------------------------------------
#define WS_H_OFF 0
#define AS_H_OFF 34816
#define RED_OFF  52224
#define SMEM_BYTES 54272
#define A_LDH 136
#define C_LDF 132

__device__ __forceinline__ void wmma_mainloop(char* smem, int w_off,
                                              const float* __restrict__ bias,
                                              int norm_off, int m0) {
    __half* Ws = (__half*)(smem + WS_H_OFF);
    __half* As = (__half*)(smem + AS_H_OFF);
    float*  C  = (float*)smem;
    int tid = threadIdx.x;

    // W fp16 (128x128) -> smem ld=136, uint4 copies
    const __half* Wh = d_wh + w_off;
#pragma unroll
    for (int j = 0; j < 8; j++) {
        int idx = j * 256 + tid;          // uint4 index, 2048 total
        int row = idx >> 4, c8 = idx & 15;  // 16 uint4 per row (128 halves)
        uint4 v = ((const uint4*)Wh)[idx];
        *(uint4*)(Ws + row * A_LDH + c8 * 8) = v;
    }
    // A tile (64x128) with per-row dst-norm scale -> fp16 smem
#pragma unroll
    for (int j = 0; j < 8; j++) {
        int idx = j * 256 + tid;          // 2048 float4
        int r = idx >> 5, c4 = idx & 31;
        int g = m0 + r;
        float4 v = make_float4(0.f, 0.f, 0.f, 0.f);
        float nm = 0.f;
        if (g < N_NODES) {
            v = *(const float4*)(d_agg + g * DIM + c4 * 4);
            nm = d_norm[norm_off + g];
        }
        __half2 h0 = __floats2half2_rn(v.x * nm, v.y * nm);
        __half2 h1 = __floats2half2_rn(v.z * nm, v.w * nm);
        uint2 st;
        st.x = *(unsigned int*)&h0;
        st.y = *(unsigned int*)&h1;
        *(uint2*)(As + r * A_LDH + c4 * 4) = st;
    }
    __syncthreads();

    int wid = tid >> 5;
    int wm = wid & 3;       // 4 row-groups of 16
    int wn = wid >> 2;      // 2 col-groups of 64

    wmma::fragment<wmma::accumulator, 16, 16, 16, float> acc[4];
#pragma unroll
    for (int n = 0; n < 4; n++) wmma::fill_fragment(acc[n], 0.f);

#pragma unroll
    for (int k = 0; k < 8; k++) {
        wmma::fragment<wmma::matrix_a, 16, 16, 16, __half, wmma::row_major> fa;
        wmma::load_matrix_sync(fa, As + (wm * 16) * A_LDH + k * 16, A_LDH);
#pragma unroll
        for (int n = 0; n < 4; n++) {
            wmma::fragment<wmma::matrix_b, 16, 16, 16, __half, wmma::row_major> fb;
            wmma::load_matrix_sync(fb, Ws + (k * 16) * A_LDH + wn * 64 + n * 16, A_LDH);
            wmma::mma_sync(acc[n], fa, fb, acc[n]);
        }
    }
    __syncthreads();   // done reading Ws/As; C aliases Ws region

#pragma unroll
    for (int n = 0; n < 4; n++)
        wmma::store_matrix_sync(C + (wm * 16) * C_LDF + wn * 64 + n * 16,
                                acc[n], C_LDF, wmma::mem_row_major);
    __syncthreads();

    // bias + ReLU in place
#pragma unroll
    for (int j = 0; j < 8; j++) {
        int idx = j * 256 + tid;
        int r = idx >> 5, c4 = idx & 31;
        float4 v = *(float4*)(C + r * C_LDF + c4 * 4);
        float4 bv = ((const float4*)bias)[c4];
        v.x = fmaxf(v.x + bv.x, 0.f);
        v.y = fmaxf(v.y + bv.y, 0.f);
        v.z = fmaxf(v.z + bv.z, 0.f);
        v.w = fmaxf(v.w + bv.w, 0.f);
        *(float4*)(C + r * C_LDF + c4 * 4) = v;
    }
    __syncthreads();
}

// GEMM1 + per-node head attention + src2-norm prescale -> d_xh (fp16)
__global__ void __launch_bounds__(256)
gemm_att_kernel(const float* __restrict__ bias) {
    extern __shared__ char smc[];
    float* As  = (float*)smc;                 // C tile
    float* red = (float*)(smc + RED_OFF);
    int tid = threadIdx.x;
    int m0 = blockIdx.x * 64;

    wmma_mainloop(smc, 0, bias, 1 * N_NODES, m0);

    {
        int row = tid >> 2, q = tid & 3;
#pragma unroll
        for (int hh = 0; hh < 2; hh++) {
            int head = q * 2 + hh;
            float s = 0.f;
#pragma unroll
            for (int c = 0; c < HDIM; c++) {
                float v = As[row * C_LDF + head * HDIM + c];
                s += v * v;
            }
            red[row * 8 + head] = s * 0.25f;   // / sqrt(HD)=4
        }
    }
    __syncthreads();
    if ((tid & 3) == 0) {
        int row = tid >> 2;
        float sc[8], mx = -1e30f;
#pragma unroll
        for (int h = 0; h < 8; h++) { sc[h] = red[row * 8 + h]; mx = fmaxf(mx, sc[h]); }
        float sum = 0.f;
#pragma unroll
        for (int h = 0; h < 8; h++) { sc[h] = expf(sc[h] - mx); sum += sc[h]; }
        float inv = 1.f / sum;
#pragma unroll
        for (int h = 0; h < 8; h++) red[row * 8 + h] = sc[h] * inv;
    }
    __syncthreads();
    {
        int row = tid >> 2, q = tid & 3;
        int g = m0 + row;
        if (g < N_NODES) {
            float nm = d_norm[2 * N_NODES + g];   // src2 norm prescale
#pragma unroll
            for (int j = 0; j < 8; j++) {
                int col = q * 32 + j * 4;
                float p = red[row * 8 + (col >> 4)] * nm;
                float4 v = *(float4*)(As + row * C_LDF + col);
                __half2 h0 = __floats2half2_rn(v.x * p, v.y * p);
                __half2 h1 = __floats2half2_rn(v.z * p, v.w * p);
                uint2 st;
                st.x = *(unsigned int*)&h0;
                st.y = *(unsigned int*)&h1;
                *(uint2*)(d_xh + g * 64 + (col >> 1)) = st;
            }
        }
    }
}

// GEMM2 + LayerNorm -> out
__global__ void __launch_bounds__(256)
gemm_ln_kernel(const float* __restrict__ bias,
               const float* __restrict__ gamma, const float* __restrict__ beta,
               float* __restrict__ out) {
    extern __shared__ char smc[];
    float* As  = (float*)smc;                 // C tile
    float* red = (float*)(smc + RED_OFF);
    int tid = threadIdx.x;
    int m0 = blockIdx.x * 64;

    wmma_mainloop(smc, DIM * DIM, bias, 3 * N_NODES, m0);

    {
        int row = tid >> 2, q = tid & 3;
        float s = 0.f, s2 = 0.f;
#pragma unroll
        for (int c = 0; c < 32; c++) {
            float v = As[row * C_LDF + q * 32 + c];
            s += v; s2 += v * v;
        }
        red[row * 8 + q] = s;
        red[row * 8 + 4 + q] = s2;
    }
    __syncthreads();
    if ((tid & 3) == 0) {
        int row = tid >> 2;
        float s = red[row * 8 + 0] + red[row * 8 + 1] + red[row * 8 + 2] + red[row * 8 + 3];
        float s2 = red[row * 8 + 4] + red[row * 8 + 5] + red[row * 8 + 6] + red[row * 8 + 7];
        float mu = s * (1.f / 128.f);
        float var = s2 * (1.f / 128.f) - mu * mu;
        red[row * 8 + 0] = mu;
        red[row * 8 + 1] = rsqrtf(var + LN_EPS);
    }
    __syncthreads();
    {
        int row = tid >> 2, q = tid & 3;
        int g = m0 + row;
        if (g < N_NODES) {
            float mu = red[row * 8 + 0];
            float rstd = red[row * 8 + 1];
#pragma unroll
            for (int j = 0; j < 8; j++) {
                int col = q * 32 + j * 4;
                float4 v = *(float4*)(As + row * C_LDF + col);
                float4 gm = ((const float4*)gamma)[col >> 2];
                float4 bt = ((const float4*)beta)[col >> 2];
                v.x = (v.x - mu) * rstd * gm.x + bt.x;
                v.y = (v.y - mu) * rstd * gm.y + bt.y;
                v.z = (v.z - mu) * rstd * gm.z + bt.z;
                v.w = (v.w - mu) * rstd * gm.w + bt.w;
                *(float4*)(out + g * DIM + col) = v;
            }
        }
    }
}

// ---------------------------------------------------------------------------
extern "C" void kernel_launch(void* const* d_in, const int* in_sizes, int n_in,
                              void* d_out, int out_size) {
    const float* feat  = (const float*)d_in[0];
    const int*   src1  = (const int*)d_in[1];
    const int*   dst1  = (const int*)d_in[2];
    const int*   src2  = (const int*)d_in[3];
    const int*   dst2  = (const int*)d_in[4];
    const float* W1    = (const float*)d_in[5];
    const float* b1    = (const float*)d_in[6];
    const float* W2    = (const float*)d_in[7];
    const float* b2    = (const float*)d_in[8];
    const float* gamma = (const float*)d_in[9];
    const float* beta  = (const float*)d_in[10];
    float* out = (float*)d_out;

    cudaFuncSetAttribute(gemm_att_kernel, cudaFuncAttributeMaxDynamicSharedMemorySize, SMEM_BYTES);
    cudaFuncSetAttribute(gemm_ln_kernel,  cudaFuncAttributeMaxDynamicSharedMemorySize, SMEM_BYTES);

    zero_deg_kernel<<<(4 * N_NODES + 255) / 256, 256>>>();
    degrees_kernel<<<(E_EDGES + 255) / 256, 256>>>(src1, dst1, src2, dst2);
    norm_bsum_kernel<<<4 * NB_PER_G, 256>>>();
    offsets_kernel<<<2 * NB_PER_G, 256>>>();
    scatter_convert_kernel<<<SCAT_BLOCKS + CONV_BLOCKS + WCONV_BLOCKS, 256>>>(
        src1, dst1, src2, dst2, feat, W1, W2);

    const int gather_blocks = (N_NODES * 16 + 255) / 256;   // half-warp per node
    gather_kernel<<<gather_blocks, 256>>>(0);
    gemm_att_kernel<<<(N_NODES + 63) / 64, 256, SMEM_BYTES>>>(b1);
    gather_kernel<<<gather_blocks, 256>>>(1);
    gemm_ln_kernel<<<(N_NODES + 63) / 64, 256, SMEM_BYTES>>>(b2, gamma, beta, out);
}

// round 9
// speedup vs baseline: 1.1157x; 1.1157x over previous
#include <cuda_runtime.h>
#include <cuda_fp16.h>
#include <mma.h>
#include <math.h>

using namespace nvcuda;

#define N_NODES 50000
#define E_EDGES 800000
#define DIM 128
#define NHEAD 8
#define HDIM 16
#define LN_EPS 1e-5f
#define FULLMASK 0xFFFFFFFFu
#define NB_PER_G ((N_NODES + 255) / 256)   // 196 blocks of 256 nodes per graph

// Scratch (static __device__ arrays: allocation-free per harness rules)
__device__ __half2 d_xh[N_NODES * 64];    // fp16 gather input, pass 1 (feat*norm_src1)
__device__ __half2 d_xh2[N_NODES * 64];   // fp16 gather input, pass 2 (attended*norm_src2)
__device__ int    d_deg[4 * N_NODES];     // [src1 | dst1 | src2 | dst2] degrees
__device__ float  d_norm[4 * N_NODES];    // rsqrt norms, same layout
__device__ int    d_off[2 * N_NODES];     // CSR row offsets [dst1 | dst2]
__device__ int    d_cur[2 * N_NODES];     // scatter cursors
__device__ int    d_csr[2 * E_EDGES];     // CSR column (source-node) ids [g1 | g2]
__device__ int    d_bsum[2 * NB_PER_G];   // per-block dst-degree sums
__device__ __half d_wh[2 * DIM * DIM];    // fp16 W1 | W2

// ---------------------------------------------------------------------------
__global__ void zero_deg_kernel() {
    int i = blockIdx.x * blockDim.x + threadIdx.x;
    if (i < 4 * N_NODES) d_deg[i] = 0;
}

__global__ void degrees_kernel(const int* __restrict__ s1, const int* __restrict__ t1,
                               const int* __restrict__ s2, const int* __restrict__ t2) {
    int i = blockIdx.x * blockDim.x + threadIdx.x;
    if (i >= E_EDGES) return;
    atomicAdd(&d_deg[0 * N_NODES + s1[i]], 1);
    atomicAdd(&d_deg[1 * N_NODES + t1[i]], 1);
    atomicAdd(&d_deg[2 * N_NODES + s2[i]], 1);
    atomicAdd(&d_deg[3 * N_NODES + t2[i]], 1);
}

// ---------------------------------------------------------------------------
// Fused: norms for all 4 segments + per-block dst-degree sums (segments 1,3).
// ---------------------------------------------------------------------------
__global__ void __launch_bounds__(256) norm_bsum_kernel() {
    int seg = blockIdx.x / NB_PER_G;          // 0:src1 1:dst1 2:src2 3:dst2
    int b   = blockIdx.x % NB_PER_G;
    int n   = b * 256 + threadIdx.x;
    int d = 0;
    if (n < N_NODES) {
        d = d_deg[seg * N_NODES + n];
        d_norm[seg * N_NODES + n] = (d > 0) ? rsqrtf((float)d) : 0.f;
    }
    if (seg == 1 || seg == 3) {
        int v = d;
#pragma unroll
        for (int o = 16; o > 0; o >>= 1) v += __shfl_down_sync(FULLMASK, v, o);
        __shared__ int ws[8];
        if ((threadIdx.x & 31) == 0) ws[threadIdx.x >> 5] = v;
        __syncthreads();
        if (threadIdx.x < 8) {
            int s = ws[threadIdx.x];
#pragma unroll
            for (int o = 4; o > 0; o >>= 1) s += __shfl_down_sync(0xFFu, s, o);
            if (threadIdx.x == 0) d_bsum[(seg >> 1) * NB_PER_G + b] = s;
        }
    }
}

// ---------------------------------------------------------------------------
// Offsets: inline prefix over d_bsum + block-local exclusive scan.
// ---------------------------------------------------------------------------
__global__ void __launch_bounds__(256) offsets_kernel() {
    __shared__ int ws[8];
    __shared__ int sbase;
    int g = blockIdx.x / NB_PER_G;
    int b = blockIdx.x % NB_PER_G;
    int degoff = (g == 0 ? 1 : 3) * N_NODES;
    int t = threadIdx.x;
    int lane = t & 31, w = t >> 5;

    {
        int v = (t < b) ? d_bsum[g * NB_PER_G + t] : 0;
#pragma unroll
        for (int o = 16; o > 0; o >>= 1) v += __shfl_down_sync(FULLMASK, v, o);
        if (lane == 0) ws[w] = v;
        __syncthreads();
        if (t < 8) {
            int s = ws[t];
#pragma unroll
            for (int o = 4; o > 0; o >>= 1) s += __shfl_down_sync(0xFFu, s, o);
            if (t == 0) sbase = s;
        }
        __syncthreads();
    }
    int blockbase = sbase;
    __syncthreads();

    int n = b * 256 + t;
    int v = (n < N_NODES) ? d_deg[degoff + n] : 0;
    int x = v;
#pragma unroll
    for (int o = 1; o < 32; o <<= 1) {
        int y = __shfl_up_sync(FULLMASK, x, o);
        if (lane >= o) x += y;
    }
    if (lane == 31) ws[w] = x;
    __syncthreads();
    if (t < 8) {
        int s = ws[t];
#pragma unroll
        for (int o = 1; o < 8; o <<= 1) {
            int y = __shfl_up_sync(0xFFu, s, o);
            if (t >= o) s += y;
        }
        ws[t] = s;
    }
    __syncthreads();
    int base = blockbase + ((w > 0) ? ws[w - 1] : 0);
    if (n < N_NODES) {
        int off = base + x - v;   // exclusive
        d_off[g * N_NODES + n] = off;
        d_cur[g * N_NODES + n] = off;
    }
}

// ---------------------------------------------------------------------------
// Fused scatter + feature convert + weight convert.
// ---------------------------------------------------------------------------
#define SCAT_BLOCKS ((2 * E_EDGES) / 256)        // 6250
#define CONV_BLOCKS ((N_NODES * 32 + 255) / 256) // 6250
#define WCONV_BLOCKS ((2 * DIM * DIM / 4) / 256) // 32
__global__ void scatter_convert_kernel(const int* __restrict__ s1, const int* __restrict__ t1,
                                       const int* __restrict__ s2, const int* __restrict__ t2,
                                       const float* __restrict__ feat,
                                       const float* __restrict__ W1,
                                       const float* __restrict__ W2) {
    int bid = blockIdx.x;
    if (bid < SCAT_BLOCKS) {
        int i = bid * 256 + threadIdx.x;
        if (i < E_EDGES) {
            int p = atomicAdd(&d_cur[0 * N_NODES + t1[i]], 1);
            d_csr[p] = s1[i];
        } else {
            int e = i - E_EDGES;
            int p = atomicAdd(&d_cur[1 * N_NODES + t2[e]], 1);
            d_csr[E_EDGES + p] = s2[e];
        }
    } else if (bid < SCAT_BLOCKS + CONV_BLOCKS) {
        int i = (bid - SCAT_BLOCKS) * 256 + threadIdx.x;
        if (i >= N_NODES * 32) return;
        int n = i >> 5, c4 = i & 31;
        float nm = d_norm[n];                       // src1 norms at offset 0
        float4 v = ((const float4*)feat)[i];
        __half2 h0 = __floats2half2_rn(v.x * nm, v.y * nm);
        __half2 h1 = __floats2half2_rn(v.z * nm, v.w * nm);
        uint2 st;
        st.x = *(unsigned int*)&h0;
        st.y = *(unsigned int*)&h1;
        *(uint2*)(d_xh + n * 64 + c4 * 2) = st;
    } else {
        int i = (bid - SCAT_BLOCKS - CONV_BLOCKS) * 256 + threadIdx.x;  // float4 idx
        const float* W = (i < 4096) ? W1 : W2;
        int li = (i < 4096) ? i : i - 4096;
        float4 v = ((const float4*)W)[li];
        __half2 h0 = __floats2half2_rn(v.x, v.y);
        __half2 h1 = __floats2half2_rn(v.z, v.w);
        uint2 st;
        st.x = *(unsigned int*)&h0;
        st.y = *(unsigned int*)&h1;
        *(uint2*)(d_wh + i * 4) = st;
    }
}

// ---------------------------------------------------------------------------
// Fused gather + tensor-core GEMM.
// Block handles 64 nodes x 128 cols, K=128. 256 threads = 8 warps = 16 half-warps.
// Phase 1: load fp16 W into smem (no sync needed vs gather).
// Phase 2: 16 half-warps CSR-gather 4 nodes each directly into fp16 A smem
//          (fp32 register accumulation, dst-norm scale, fp16 store).
//          Gather INPUT buffer is selected per pass (d_xh / d_xh2) — pass 1's
//          epilogue writes d_xh2, so no read/write hazard within a launch.
// Phase 3: wmma mainloop; C (fp32) aliases Ws region; bias+ReLU epilogue.
// smem layout (bytes):
//   [0, 34816)       Ws_h: half[128][136]  -- later aliased by C (fp32 64x132)
//   [34816, 52224)   As_h: half[64][136]
//   [52224, 54272)   red:  float[512]
// ---------------------------------------------------------------------------
#define WS_H_OFF 0
#define AS_H_OFF 34816
#define RED_OFF  52224
#define SMEM_BYTES 54272
#define A_LDH 136
#define C_LDF 132

__device__ __forceinline__ void acc_half16(float4& a0, float4& a1, uint4 r) {
    __half2 h0 = *(__half2*)&r.x;
    __half2 h1 = *(__half2*)&r.y;
    __half2 h2 = *(__half2*)&r.z;
    __half2 h3 = *(__half2*)&r.w;
    float2 f0 = __half22float2(h0);
    float2 f1 = __half22float2(h1);
    float2 f2 = __half22float2(h2);
    float2 f3 = __half22float2(h3);
    a0.x += f0.x; a0.y += f0.y; a0.z += f1.x; a0.w += f1.y;
    a1.x += f2.x; a1.y += f2.y; a1.z += f3.x; a1.w += f3.y;
}

__device__ __forceinline__ void gather_gemm_mainloop(char* smem, int graph, int w_off,
                                                     const __half2* __restrict__ base,
                                                     const float* __restrict__ bias,
                                                     int norm_off, int m0) {
    __half* Ws = (__half*)(smem + WS_H_OFF);
    __half* As = (__half*)(smem + AS_H_OFF);
    float*  C  = (float*)smem;
    int tid = threadIdx.x;

    // --- Phase 1: W fp16 (128x128) -> smem ld=136 (uint4 copies) ---
    const __half* Wh = d_wh + w_off;
#pragma unroll
    for (int j = 0; j < 8; j++) {
        int idx = j * 256 + tid;            // uint4 index, 2048 total
        int row = idx >> 4, c8 = idx & 15;  // 16 uint4 per row (128 halves)
        uint4 v = ((const uint4*)Wh)[idx];
        *(uint4*)(Ws + row * A_LDH + c8 * 8) = v;
    }

    // --- Phase 2: CSR gather directly into fp16 A smem ---
    int hw = tid >> 4;                       // half-warp 0..15
    int lane16 = tid & 15;
    unsigned hmask = 0xFFFFu << (tid & 16);
    int degseg = (graph == 0 ? 1 : 3) * N_NODES;
    const int* csr = d_csr + graph * E_EDGES;

#pragma unroll
    for (int k = 0; k < 4; k++) {
        int n_local = k * 16 + hw;
        int gnode = m0 + n_local;
        float4 accA0 = make_float4(0.f,0.f,0.f,0.f), accA1 = make_float4(0.f,0.f,0.f,0.f);
        float4 accB0 = make_float4(0.f,0.f,0.f,0.f), accB1 = make_float4(0.f,0.f,0.f,0.f);
        float4 accC0 = make_float4(0.f,0.f,0.f,0.f), accC1 = make_float4(0.f,0.f,0.f,0.f);
        float4 accD0 = make_float4(0.f,0.f,0.f,0.f), accD1 = make_float4(0.f,0.f,0.f,0.f);
        float nm = 0.f;
        if (gnode < N_NODES) {
            nm = d_norm[norm_off + gnode];
            int beg = d_off[graph * N_NODES + gnode];
            int cnt = d_deg[degseg + gnode];
            for (int j0 = 0; j0 < cnt; j0 += 16) {
                int m = min(16, cnt - j0);
                int s_l = (lane16 < m) ? csr[beg + j0 + lane16] : 0;
                int jj = 0;
                for (; jj + 3 < m; jj += 4) {
                    int sA = __shfl_sync(hmask, s_l, jj,     16);
                    int sB = __shfl_sync(hmask, s_l, jj + 1, 16);
                    int sC = __shfl_sync(hmask, s_l, jj + 2, 16);
                    int sD = __shfl_sync(hmask, s_l, jj + 3, 16);
                    uint4 rA = *(const uint4*)(base + sA * 64 + lane16 * 4);
                    uint4 rB = *(const uint4*)(base + sB * 64 + lane16 * 4);
                    uint4 rC = *(const uint4*)(base + sC * 64 + lane16 * 4);
                    uint4 rD = *(const uint4*)(base + sD * 64 + lane16 * 4);
                    acc_half16(accA0, accA1, rA);
                    acc_half16(accB0, accB1, rB);
                    acc_half16(accC0, accC1, rC);
                    acc_half16(accD0, accD1, rD);
                }
                for (; jj < m; jj++) {
                    int sA = __shfl_sync(hmask, s_l, jj, 16);
                    uint4 rA = *(const uint4*)(base + sA * 64 + lane16 * 4);
                    acc_half16(accA0, accA1, rA);
                }
            }
        }
        accA0.x += accB0.x + accC0.x + accD0.x;
        accA0.y += accB0.y + accC0.y + accD0.y;
        accA0.z += accB0.z + accC0.z + accD0.z;
        accA0.w += accB0.w + accC0.w + accD0.w;
        accA1.x += accB1.x + accC1.x + accD1.x;
        accA1.y += accB1.y + accC1.y + accD1.y;
        accA1.z += accB1.z + accC1.z + accD1.z;
        accA1.w += accB1.w + accC1.w + accD1.w;
        __half2 h0 = __floats2half2_rn(accA0.x * nm, accA0.y * nm);
        __half2 h1 = __floats2half2_rn(accA0.z * nm, accA0.w * nm);
        __half2 h2 = __floats2half2_rn(accA1.x * nm, accA1.y * nm);
        __half2 h3 = __floats2half2_rn(accA1.z * nm, accA1.w * nm);
        uint4 st;
        st.x = *(unsigned int*)&h0;
        st.y = *(unsigned int*)&h1;
        st.z = *(unsigned int*)&h2;
        st.w = *(unsigned int*)&h3;
        *(uint4*)(As + n_local * A_LDH + lane16 * 8) = st;
    }
    __syncthreads();

    // --- Phase 3: wmma mainloop ---
    int wid = tid >> 5;
    int wm = wid & 3;       // 4 row-groups of 16
    int wn = wid >> 2;      // 2 col-groups of 64

    wmma::fragment<wmma::accumulator, 16, 16, 16, float> acc[4];
#pragma unroll
    for (int n = 0; n < 4; n++) wmma::fill_fragment(acc[n], 0.f);

#pragma unroll
    for (int k = 0; k < 8; k++) {
        wmma::fragment<wmma::matrix_a, 16, 16, 16, __half, wmma::row_major> fa;
        wmma::load_matrix_sync(fa, As + (wm * 16) * A_LDH + k * 16, A_LDH);
#pragma unroll
        for (int n = 0; n < 4; n++) {
            wmma::fragment<wmma::matrix_b, 16, 16, 16, __half, wmma::row_major> fb;
            wmma::load_matrix_sync(fb, Ws + (k * 16) * A_LDH + wn * 64 + n * 16, A_LDH);
            wmma::mma_sync(acc[n], fa, fb, acc[n]);
        }
    }
    __syncthreads();   // done reading Ws/As; C aliases Ws region

#pragma unroll
    for (int n = 0; n < 4; n++)
        wmma::store_matrix_sync(C + (wm * 16) * C_LDF + wn * 64 + n * 16,
                                acc[n], C_LDF, wmma::mem_row_major);
    __syncthreads();

    // bias + ReLU in place
#pragma unroll
    for (int j = 0; j < 8; j++) {
        int idx = j * 256 + tid;
        int r = idx >> 5, c4 = idx & 31;
        float4 v = *(float4*)(C + r * C_LDF + c4 * 4);
        float4 bv = ((const float4*)bias)[c4];
        v.x = fmaxf(v.x + bv.x, 0.f);
        v.y = fmaxf(v.y + bv.y, 0.f);
        v.z = fmaxf(v.z + bv.z, 0.f);
        v.w = fmaxf(v.w + bv.w, 0.f);
        *(float4*)(C + r * C_LDF + c4 * 4) = v;
    }
    __syncthreads();
}

// gather(g1, from d_xh) + GEMM1 + attention + src2-norm prescale -> d_xh2 (fp16)
__global__ void __launch_bounds__(256)
gemm_att_kernel(const float* __restrict__ bias) {
    extern __shared__ char smc[];
    float* As  = (float*)smc;                 // C tile
    float* red = (float*)(smc + RED_OFF);
    int tid = threadIdx.x;
    int m0 = blockIdx.x * 64;

    gather_gemm_mainloop(smc, 0, 0, d_xh, bias, 1 * N_NODES, m0);

    {
        int row = tid >> 2, q = tid & 3;
#pragma unroll
        for (int hh = 0; hh < 2; hh++) {
            int head = q * 2 + hh;
            float s = 0.f;
#pragma unroll
            for (int c = 0; c < HDIM; c++) {
                float v = As[row * C_LDF + head * HDIM + c];
                s += v * v;
            }
            red[row * 8 + head] = s * 0.25f;   // / sqrt(HD)=4
        }
    }
    __syncthreads();
    if ((tid & 3) == 0) {
        int row = tid >> 2;
        float sc[8], mx = -1e30f;
#pragma unroll
        for (int h = 0; h < 8; h++) { sc[h] = red[row * 8 + h]; mx = fmaxf(mx, sc[h]); }
        float sum = 0.f;
#pragma unroll
        for (int h = 0; h < 8; h++) { sc[h] = expf(sc[h] - mx); sum += sc[h]; }
        float inv = 1.f / sum;
#pragma unroll
        for (int h = 0; h < 8; h++) red[row * 8 + h] = sc[h] * inv;
    }
    __syncthreads();
    {
        int row = tid >> 2, q = tid & 3;
        int g = m0 + row;
        if (g < N_NODES) {
            float nm = d_norm[2 * N_NODES + g];   // src2 norm prescale
#pragma unroll
            for (int j = 0; j < 8; j++) {
                int col = q * 32 + j * 4;
                float p = red[row * 8 + (col >> 4)] * nm;
                float4 v = *(float4*)(As + row * C_LDF + col);
                __half2 h0 = __floats2half2_rn(v.x * p, v.y * p);
                __half2 h1 = __floats2half2_rn(v.z * p, v.w * p);
                uint2 st;
                st.x = *(unsigned int*)&h0;
                st.y = *(unsigned int*)&h1;
                *(uint2*)(d_xh2 + g * 64 + (col >> 1)) = st;   // double buffer: no WAR race
            }
        }
    }
}

// gather(g2, from d_xh2) + GEMM2 + LayerNorm -> out
__global__ void __launch_bounds__(256)
gemm_ln_kernel(const float* __restrict__ bias,
               const float* __restrict__ gamma, const float* __restrict__ beta,
               float* __restrict__ out) {
    extern __shared__ char smc[];
    float* As  = (float*)smc;                 // C tile
    float* red = (float*)(smc + RED_OFF);
    int tid = threadIdx.x;
    int m0 = blockIdx.x * 64;

    gather_gemm_mainloop(smc, 1, DIM * DIM, d_xh2, bias, 3 * N_NODES, m0);

    {
        int row = tid >> 2, q = tid & 3;
        float s = 0.f, s2 = 0.f;
#pragma unroll
        for (int c = 0; c < 32; c++) {
            float v = As[row * C_LDF + q * 32 + c];
            s += v; s2 += v * v;
        }
        red[row * 8 + q] = s;
        red[row * 8 + 4 + q] = s2;
    }
    __syncthreads();
    if ((tid & 3) == 0) {
        int row = tid >> 2;
        float s = red[row * 8 + 0] + red[row * 8 + 1] + red[row * 8 + 2] + red[row * 8 + 3];
        float s2 = red[row * 8 + 4] + red[row * 8 + 5] + red[row * 8 + 6] + red[row * 8 + 7];
        float mu = s * (1.f / 128.f);
        float var = s2 * (1.f / 128.f) - mu * mu;
        red[row * 8 + 0] = mu;
        red[row * 8 + 1] = rsqrtf(var + LN_EPS);
    }
    __syncthreads();
    {
        int row = tid >> 2, q = tid & 3;
        int g = m0 + row;
        if (g < N_NODES) {
            float mu = red[row * 8 + 0];
            float rstd = red[row * 8 + 1];
#pragma unroll
            for (int j = 0; j < 8; j++) {
                int col = q * 32 + j * 4;
                float4 v = *(float4*)(As + row * C_LDF + col);
                float4 gm = ((const float4*)gamma)[col >> 2];
                float4 bt = ((const float4*)beta)[col >> 2];
                v.x = (v.x - mu) * rstd * gm.x + bt.x;
                v.y = (v.y - mu) * rstd * gm.y + bt.y;
                v.z = (v.z - mu) * rstd * gm.z + bt.z;
                v.w = (v.w - mu) * rstd * gm.w + bt.w;
                *(float4*)(out + g * DIM + col) = v;
            }
        }
    }
}

// ---------------------------------------------------------------------------
extern "C" void kernel_launch(void* const* d_in, const int* in_sizes, int n_in,
                              void* d_out, int out_size) {
    const float* feat  = (const float*)d_in[0];
    const int*   src1  = (const int*)d_in[1];
    const int*   dst1  = (const int*)d_in[2];
    const int*   src2  = (const int*)d_in[3];
    const int*   dst2  = (const int*)d_in[4];
    const float* W1    = (const float*)d_in[5];
    const float* b1    = (const float*)d_in[6];
    const float* W2    = (const float*)d_in[7];
    const float* b2    = (const float*)d_in[8];
    const float* gamma = (const float*)d_in[9];
    const float* beta  = (const float*)d_in[10];
    float* out = (float*)d_out;

    cudaFuncSetAttribute(gemm_att_kernel, cudaFuncAttributeMaxDynamicSharedMemorySize, SMEM_BYTES);
    cudaFuncSetAttribute(gemm_ln_kernel,  cudaFuncAttributeMaxDynamicSharedMemorySize, SMEM_BYTES);

    zero_deg_kernel<<<(4 * N_NODES + 255) / 256, 256>>>();
    degrees_kernel<<<(E_EDGES + 255) / 256, 256>>>(src1, dst1, src2, dst2);
    norm_bsum_kernel<<<4 * NB_PER_G, 256>>>();
    offsets_kernel<<<2 * NB_PER_G, 256>>>();
    scatter_convert_kernel<<<SCAT_BLOCKS + CONV_BLOCKS + WCONV_BLOCKS, 256>>>(
        src1, dst1, src2, dst2, feat, W1, W2);

    gemm_att_kernel<<<(N_NODES + 63) / 64, 256, SMEM_BYTES>>>(b1);
    gemm_ln_kernel<<<(N_NODES + 63) / 64, 256, SMEM_BYTES>>>(b2, gamma, beta, out);
}